// round 10
// baseline (speedup 1.0000x reference)
#include <cuda_runtime.h>
#include <cstdint>
#include <math.h>

#define THREADS 256
#define NBLOCKS 4096

// ---- smem (32-bit words) ----
// xtile[4 pairs][3072] : per-pair fragment-major tf32 X (16 px x 192 ch)
// dstg [4 pairs][1280] : GEMM2 cross-half partials [64 col][20 pad]
// gstg [4 pairs][192]  : gate partials [half][q(6)][r(2)][g(8)]
#define XT_OFF 0
#define DS_OFF 12288
#define GS_OFF (DS_OFF + 5120)
#define SM_B1S (GS_OFF + 768)
#define SM_W2S (SM_B1S + 64)
#define SM_BFS (SM_W2S + 64)
#define SM_FLOATS (SM_BFS + 64)
#define SM_BYTES (SM_FLOATS * 4)      // 74112 B -> 2 CTAs/SM

__device__ __align__(16) uint32_t g_w1_frag[8192];
__device__ __align__(16) uint32_t g_wf_frag[12288];

__device__ __forceinline__ uint32_t f2tf32(float v) {
    uint32_t o;
    asm("cvt.rna.tf32.f32 %0, %1;" : "=r"(o) : "f"(v));
    return o;
}
__device__ __forceinline__ void mma8(float d[4], const uint32_t a[4],
                                     uint32_t b0, uint32_t b1) {
    asm volatile(
        "mma.sync.aligned.m16n8k8.row.col.f32.tf32.tf32.f32 "
        "{%0,%1,%2,%3}, {%4,%5,%6,%7}, {%8,%9}, {%0,%1,%2,%3};"
        : "+f"(d[0]), "+f"(d[1]), "+f"(d[2]), "+f"(d[3])
        : "r"(a[0]), "r"(a[1]), "r"(a[2]), "r"(a[3]), "r"(b0), "r"(b1));
}
__device__ __forceinline__ float gelu_b(float h) {
    const float z = h * fmaf(h * h, 0.07056f, 1.5976f);
    return __fdividef(h, 1.0f + __expf(-z));
}
__device__ __forceinline__ void pair_bar(int id) {
    asm volatile("bar.sync %0, 64;" :: "r"(id) : "memory");
}

__global__ void __launch_bounds__(512)
prep_w(const float* __restrict__ W1, const float* __restrict__ Wf) {
    int i = blockIdx.x * 512 + threadIdx.x;
    if (i < 8192) {
        int r = i >> 6, e = i & 63;
        int n = (r < 64) ? e : (64 + e);
        int k = r & 63;
        int addr = ((k >> 3) * 16 + (n >> 3)) * 64 + ((n & 7) * 4 + (k & 3)) * 2 + ((k >> 2) & 1);
        g_w1_frag[addr] = f2tf32(W1[i]);
    } else if (i < 8192 + 12288) {
        int j = i - 8192;
        int r = j >> 6, c = j & 63;
        int addr = ((r >> 3) * 8 + (c >> 3)) * 64 + ((c & 7) * 4 + (r & 3)) * 2 + ((r >> 2) & 1);
        g_wf_frag[addr] = f2tf32(Wf[j]);
    }
}

__global__ void __launch_bounds__(THREADS, 2)
dig_mma8(const float* __restrict__ deg,
         const float* __restrict__ b1,
         const float* __restrict__ W2,
         const float* __restrict__ b2,
         const float* __restrict__ bf,
         float* __restrict__ out)
{
    extern __shared__ float sm[];
    uint32_t* xw  = (uint32_t*)sm;
    float*    dsg = sm + DS_OFF;
    float*    gsg = sm + GS_OFF;
    float*    b1s = sm + SM_B1S;
    float*    w2s = sm + SM_W2S;
    float*    bfs = sm + SM_BFS;

    const int tid  = threadIdx.x;
    const int wid  = tid >> 5;
    const int lane = tid & 31;
    const int g    = lane >> 2;
    const int tig  = lane & 3;
    const int pair = wid >> 1;       // 0..3, owns 16 pixels
    const int half = wid & 1;        // e-half (GEMM1) / k-half (GEMM2)
    const int px0  = pair << 4;
    const int barid = pair + 1;

    const int bb  = blockIdx.x >> 10;
    const int hw0 = (blockIdx.x & 1023) << 6;

    uint32_t* xt = xw + pair * 3072;

    // ------- stage per-pair X tile into fragment-major layout -------
    {
        const float* dptr = deg + (size_t)bb * 192 * 65536 + hw0 + px0;
        #pragma unroll
        for (int j = 0; j < 12; j++) {
            const int s = j * 64 + half * 32 + lane;   // 0..767
            const int koct = s >> 5;
            const int ls   = s & 31;
            const int p0 = ls >> 2;
            const int c0 = (koct << 3) + (ls & 3);
            const float* q = dptr + (size_t)c0 * 65536 + p0;
            uint4 w;
            w.x = f2tf32(q[0]);
            w.y = f2tf32(q[8]);
            w.z = f2tf32(q[(size_t)4 * 65536]);
            w.w = f2tf32(q[(size_t)4 * 65536 + 8]);
            *(uint4*)(xt + s * 4) = w;
        }
    }
    if (tid < 64) { b1s[tid] = b1[tid]; w2s[tid] = W2[tid]; bfs[tid] = bf[tid]; }
    __syncthreads();    // the ONLY block-wide barrier

    const uint32_t* xfr = xt + lane * 4;

    // -------- GEMM1 (tf32 MMA, B from L2) + in-register gating --------
    float sp[6][2] = {{0.f,0.f},{0.f,0.f},{0.f,0.f},{0.f,0.f},{0.f,0.f},{0.f,0.f}};
    const uint32_t* b1g = g_w1_frag + lane * 2;
    #pragma unroll
    for (int qq = 0; qq < 2; qq++) {
        const int qt = half * 2 + qq;
        float accA[3][2][4], accC[3][2][4];
        #pragma unroll
        for (int t = 0; t < 3; t++)
            #pragma unroll
            for (int n = 0; n < 2; n++)
                #pragma unroll
                for (int r = 0; r < 4; r++) { accA[t][n][r] = 0.f; accC[t][n][r] = 0.f; }

        #pragma unroll
        for (int k = 0; k < 8; k++) {
            uint32_t af[3][4];
            #pragma unroll
            for (int t = 0; t < 3; t++) {
                uint4 v = *(const uint4*)(xfr + (t * 8 + k) * 128);
                af[t][0] = v.x; af[t][1] = v.y; af[t][2] = v.z; af[t][3] = v.w;
            }
            #pragma unroll
            for (int nt = 0; nt < 2; nt++) {
                const int nb = qt * 2 + nt;
                uint2 av = __ldg((const uint2*)(b1g + (k * 16 + nb) * 64));
                #pragma unroll
                for (int t = 0; t < 3; t++) mma8(accA[t][nt], af[t], av.x, av.y);
                uint2 cv = __ldg((const uint2*)(b1g + (k * 16 + 8 + nb) * 64));
                #pragma unroll
                for (int t = 0; t < 3; t++) mma8(accC[t][nt], af[t], cv.x, cv.y);
            }
        }
        #pragma unroll
        for (int nt = 0; nt < 2; nt++) {
            #pragma unroll
            for (int cc = 0; cc < 2; cc++) {
                const int e = qt * 16 + nt * 8 + 2 * tig + cc;
                const float bbv = b1s[e];
                const float wv  = w2s[e];
                #pragma unroll
                for (int r = 0; r < 2; r++) {
                    const int ri = 2 * r + cc;
                    sp[0][r] = fmaf(gelu_b(accA[0][nt][ri] + accC[1][nt][ri] + bbv), wv, sp[0][r]);
                    sp[1][r] = fmaf(gelu_b(accA[0][nt][ri] + accC[2][nt][ri] + bbv), wv, sp[1][r]);
                    sp[2][r] = fmaf(gelu_b(accA[1][nt][ri] + accC[0][nt][ri] + bbv), wv, sp[2][r]);
                    sp[3][r] = fmaf(gelu_b(accA[1][nt][ri] + accC[2][nt][ri] + bbv), wv, sp[3][r]);
                    sp[4][r] = fmaf(gelu_b(accA[2][nt][ri] + accC[0][nt][ri] + bbv), wv, sp[4][r]);
                    sp[5][r] = fmaf(gelu_b(accA[2][nt][ri] + accC[1][nt][ri] + bbv), wv, sp[5][r]);
                }
            }
        }
    }
    // quad butterfly reduce (all lanes get quad sum), stage per-half partials
    {
        float* gp = gsg + pair * 192 + half * 96;
        #pragma unroll
        for (int q = 0; q < 6; q++) {
            #pragma unroll
            for (int r = 0; r < 2; r++) {
                float v = sp[q][r];
                v += __shfl_xor_sync(0xffffffffu, v, 1, 4);
                v += __shfl_xor_sync(0xffffffffu, v, 2, 4);
                if (tig == 0) gp[(q * 2 + r) * 8 + g] = v;
            }
        }
    }
    pair_bar(barid);

    // gate scalars for this thread's two rows (g, g+8)
    float mm[2][6];
    {
        const float b2v = __ldg(b2);
        const float* g0 = gsg + pair * 192;
        #pragma unroll
        for (int q = 0; q < 6; q++) {
            #pragma unroll
            for (int r = 0; r < 2; r++) {
                float v = g0[(q * 2 + r) * 8 + g] + g0[96 + (q * 2 + r) * 8 + g] + b2v;
                mm[r][q] = 1.0f / (1.0f + __expf(-v));
            }
        }
    }

    // -------- GEMM2 with fused Y-mix: k-half per warp, full n --------
    float D[8][4];
    #pragma unroll
    for (int n = 0; n < 8; n++)
        #pragma unroll
        for (int r = 0; r < 4; r++) D[n][r] = 0.f;

    {
        const uint32_t* b2g = g_wf_frag + lane * 2;
        const int dd0 = half * 4;
        #pragma unroll
        for (int dd = dd0; dd < dd0 + 4; dd++) {
            float xf[3][4];
            #pragma unroll
            for (int t = 0; t < 3; t++) {
                uint4 v = *(const uint4*)(xfr + (t * 8 + dd) * 128);
                xf[t][0] = __uint_as_float(v.x);
                xf[t][1] = __uint_as_float(v.y);
                xf[t][2] = __uint_as_float(v.z);
                xf[t][3] = __uint_as_float(v.w);
            }
            #pragma unroll
            for (int t = 0; t < 3; t++) {
                const int u1 = (t == 0) ? 1 : 0;
                const int u2 = (t == 2) ? 1 : 2;
                uint32_t yf[4];
                #pragma unroll
                for (int r = 0; r < 4; r++) {
                    const int row = r & 1;
                    float y = fmaf(mm[row][2 * t + 1], xf[u2][r],
                              fmaf(mm[row][2 * t],     xf[u1][r], xf[t][r]));
                    yf[r] = f2tf32(y);
                }
                const int kk = t * 8 + dd;
                #pragma unroll
                for (int n = 0; n < 8; n++) {
                    uint2 bv = __ldg((const uint2*)(b2g + (kk * 8 + n) * 64));
                    mma8(D[n], yf, bv.x, bv.y);
                }
            }
        }
    }

    // -------- symmetric cross-half combine within the pair --------
    // warp `half` stages n-tiles [(1-half)*4, ..), finalizes n-tiles [half*4, ..)
    {
        float* ds = dsg + pair * 1280;   // [64 col][20]
        const int ns = (1 - half) * 4;
        #pragma unroll
        for (int n = ns; n < ns + 4; n++) {
            #pragma unroll
            for (int cc = 0; cc < 2; cc++) {
                const int col = n * 8 + 2 * tig + cc;
                ds[col * 20 + g]     = D[n][cc];
                ds[col * 20 + g + 8] = D[n][2 + cc];
            }
        }
        pair_bar(barid);

        float* op = out + (size_t)bb * 64 * 65536 + hw0 + px0;
        const int nf = half * 4;
        #pragma unroll
        for (int n = nf; n < nf + 4; n++) {
            #pragma unroll
            for (int cc = 0; cc < 2; cc++) {
                const int col = n * 8 + 2 * tig + cc;
                const float bfv = bfs[col];
                float v0 = D[n][cc]     + ds[col * 20 + g]     + bfv;
                float v1 = D[n][2 + cc] + ds[col * 20 + g + 8] + bfv;
                op[(size_t)col * 65536 + g]     = v0;
                op[(size_t)col * 65536 + g + 8] = v1;
            }
        }
    }
}

extern "C" void kernel_launch(void* const* d_in, const int* in_sizes, int n_in,
                              void* d_out, int out_size)
{
    const float* deg = (const float*)d_in[0];
    const float* W1  = (const float*)d_in[1];
    const float* b1  = (const float*)d_in[2];
    const float* W2  = (const float*)d_in[3];
    const float* b2  = (const float*)d_in[4];
    const float* Wf  = (const float*)d_in[5];
    const float* bf  = (const float*)d_in[6];
    float* outp = (float*)d_out;

    prep_w<<<40, 512>>>(W1, Wf);
    cudaFuncSetAttribute(dig_mma8, cudaFuncAttributeMaxDynamicSharedMemorySize, SM_BYTES);
    dig_mma8<<<NBLOCKS, THREADS, SM_BYTES>>>(deg, b1, W2, b2, bf, outp);
}